// round 2
// baseline (speedup 1.0000x reference)
#include <cuda_runtime.h>
#include <math.h>

#define LOG_HI 4.605170185988092f   // log(100)
#define LOG_LO (-4.605170185988092f) // log(0.01)

// ---------------- scratch (device globals; no allocation allowed) ----------------
__device__ float g_cat[256u * 256u * 480u];    // squeeze output (also +0.1*proc folded at conv load)
__device__ float g_t0 [256u * 256u * 480u];    // pose0 out
__device__ float g_t1 [256u * 256u * 480u];    // pose1 out
__device__ float g_s1 [256u * 128u * 480u];    // scale1 out
__device__ float g_s2 [256u * 64u  * 480u];    // scale2 out
__device__ float g_pooled[256 * 256];
__device__ float g_bninv[1000];
__device__ float g_proc[256 * 256];            // 0.1 * proc
__device__ float g_t1pool[256 * 256];
__device__ float g_out12[256 * 12];
__device__ float g_sfeat[256 * 64];

// ---------------- squeeze: 1x1 conv 512->256 + ReLU ----------------
// grid (5 ptile, 4 cotile, 256 b), block 256
__global__ void squeeze_kernel(const float* __restrict__ f0,
                               const float* __restrict__ w,
                               const float* __restrict__ bias)
{
    const int b  = blockIdx.z;
    const int co0 = blockIdx.y * 64;
    const int p0  = blockIdx.x * 96;
    const int t  = threadIdx.x;
    const int tx = t & 15;       // pos group: 6 cols each
    const int ty = t >> 4;       // co group: 4 co each

    __shared__ float sw[16][65];     // [kk][co]
    __shared__ float sx[16][96];     // [kk][pp]

    float acc[4][6];
#pragma unroll
    for (int i = 0; i < 4; i++)
#pragma unroll
        for (int j = 0; j < 6; j++) acc[i][j] = 0.f;

    const float* f0b = f0 + (size_t)b * 512u * 480u;

    for (int k0 = 0; k0 < 512; k0 += 16) {
        __syncthreads();
        // weights: 64co x 16kk. global: w[(co0+co)*512 + k0+kk] (kk contiguous)
        for (int idx = t; idx < 64 * 16; idx += 256) {
            int co = idx >> 4;
            int kk = idx & 15;
            sw[kk][co] = w[(size_t)(co0 + co) * 512u + k0 + kk];
        }
        // inputs: 16kk x 96pp
        for (int idx = t; idx < 16 * 96; idx += 256) {
            int kk = idx / 96;
            int pp = idx % 96;
            sx[kk][pp] = f0b[(size_t)(k0 + kk) * 480u + p0 + pp];
        }
        __syncthreads();
#pragma unroll
        for (int kk = 0; kk < 16; kk++) {
            float wv[4], xv[6];
#pragma unroll
            for (int i = 0; i < 4; i++) wv[i] = sw[kk][ty * 4 + i];
#pragma unroll
            for (int j = 0; j < 6; j++) xv[j] = sx[kk][tx * 6 + j];
#pragma unroll
            for (int i = 0; i < 4; i++)
#pragma unroll
                for (int j = 0; j < 6; j++)
                    acc[i][j] = fmaf(wv[i], xv[j], acc[i][j]);
        }
    }

#pragma unroll
    for (int i = 0; i < 4; i++) {
        int co = co0 + ty * 4 + i;
        float bb = bias[co];
#pragma unroll
        for (int j = 0; j < 6; j++) {
            float v = fmaxf(acc[i][j] + bb, 0.f);
            g_cat[((size_t)b * 256u + co) * 480u + p0 + tx * 6 + j] = v;
        }
    }
}

// ---------------- generic mean-over-480 pool (one warp per row) ----------------
__global__ void pool_kernel(const float* __restrict__ src, float* __restrict__ dst, int rows)
{
    int r = blockIdx.x * 8 + (threadIdx.x >> 5);
    int lane = threadIdx.x & 31;
    if (r >= rows) return;
    const float* p = src + (size_t)r * 480u;
    float s = 0.f;
    for (int i = lane; i < 480; i += 32) s += p[i];
#pragma unroll
    for (int o = 16; o > 0; o >>= 1) s += __shfl_xor_sync(0xffffffffu, s, o);
    if (lane == 0) dst[r] = s * (1.0f / 480.0f);
}

// ---------------- feature bank inverse norms ----------------
__global__ void banknorm_kernel(const float* __restrict__ bank)
{
    int r = blockIdx.x * 8 + (threadIdx.x >> 5);
    int lane = threadIdx.x & 31;
    if (r >= 1000) return;
    float s = 0.f;
    for (int c = lane; c < 256; c += 32) {
        float v = bank[(size_t)r * 256u + c];
        s += v * v;
    }
#pragma unroll
    for (int o = 16; o > 0; o >>= 1) s += __shfl_xor_sync(0xffffffffu, s, o);
    if (lane == 0) g_bninv[r] = 1.0f / fmaxf(sqrtf(s), 1e-12f);
}

// ---------------- KNN + fusion MLP: one block per batch row ----------------
__global__ void knn_fusion_kernel(const float* __restrict__ bank,
                                  const float* __restrict__ W1, const float* __restrict__ b1,
                                  const float* __restrict__ W2, const float* __restrict__ b2)
{
    const int b = blockIdx.x;
    const int t = threadIdx.x;
    const int lane = t & 31;
    const int wid = t >> 5;

    __shared__ float q[256];
    __shared__ float sims[1000];
    __shared__ float red[8];
    __shared__ float rv[8]; __shared__ int ri[8];
    __shared__ float topv[5]; __shared__ int topi[5];
    __shared__ float wts[5];
    __shared__ float fused[512];
    __shared__ float h[256];

    q[t] = g_pooled[b * 256 + t];
    __syncthreads();

    // ||q||
    float x = q[t] * q[t];
#pragma unroll
    for (int o = 16; o > 0; o >>= 1) x += __shfl_xor_sync(0xffffffffu, x, o);
    if (lane == 0) red[wid] = x;
    __syncthreads();
    if (t == 0) {
        float s = 0.f;
        for (int i = 0; i < 8; i++) s += red[i];
        red[0] = 1.0f / fmaxf(sqrtf(s), 1e-12f);
    }
    __syncthreads();
    const float qinv = red[0];

    // sims: warp per bank row (coalesced)
    for (int r = wid; r < 1000; r += 8) {
        float s = 0.f;
        const float* br = bank + (size_t)r * 256u;
        for (int c = lane; c < 256; c += 32) s += q[c] * br[c];
#pragma unroll
        for (int o = 16; o > 0; o >>= 1) s += __shfl_xor_sync(0xffffffffu, s, o);
        if (lane == 0) sims[r] = s * qinv * g_bninv[r];
    }
    __syncthreads();

    // top-5 via 5 block-wide argmax rounds (tie -> lower index, matching top_k)
    for (int k = 0; k < 5; k++) {
        float bv = -1e30f; int bi = 0x7fffffff;
        for (int r = t; r < 1000; r += 256) {
            float v = sims[r];
            if (v > bv || (v == bv && r < bi)) { bv = v; bi = r; }
        }
#pragma unroll
        for (int o = 16; o > 0; o >>= 1) {
            float ov = __shfl_xor_sync(0xffffffffu, bv, o);
            int oi   = __shfl_xor_sync(0xffffffffu, bi, o);
            if (ov > bv || (ov == bv && oi < bi)) { bv = ov; bi = oi; }
        }
        if (lane == 0) { rv[wid] = bv; ri[wid] = bi; }
        __syncthreads();
        if (t == 0) {
            float mv = rv[0]; int mi = ri[0];
            for (int i = 1; i < 8; i++)
                if (rv[i] > mv || (rv[i] == mv && ri[i] < mi)) { mv = rv[i]; mi = ri[i]; }
            topv[k] = mv; topi[k] = mi;
            sims[mi] = -1e30f;
        }
        __syncthreads();
    }

    // softmax over top-5 (descending, so topv[0] is the max)
    if (t == 0) {
        float m = topv[0];
        float s = 0.f;
        for (int k = 0; k < 5; k++) { wts[k] = expf(topv[k] - m); s += wts[k]; }
        float inv = 1.0f / s;
        for (int k = 0; k < 5; k++) wts[k] *= inv;
    }
    __syncthreads();

    // fused = [pooled, wnf]
    fused[t] = q[t];
    {
        float a = 0.f;
#pragma unroll
        for (int k = 0; k < 5; k++) a += wts[k] * bank[(size_t)topi[k] * 256u + t];
        fused[256 + t] = a;
    }
    __syncthreads();

    // h = relu(W1 @ fused + b1) : warp per output row
    for (int j = wid; j < 256; j += 8) {
        float s = 0.f;
        const float* wr = W1 + (size_t)j * 512u;
        for (int i = lane; i < 512; i += 32) s += fused[i] * wr[i];
#pragma unroll
        for (int o = 16; o > 0; o >>= 1) s += __shfl_xor_sync(0xffffffffu, s, o);
        if (lane == 0) h[j] = fmaxf(s + b1[j], 0.f);
    }
    __syncthreads();

    // proc = W2 @ h + b2 ; store 0.1*proc
    for (int j = wid; j < 256; j += 8) {
        float s = 0.f;
        const float* wr = W2 + (size_t)j * 256u;
        for (int i = lane; i < 256; i += 32) s += h[i] * wr[i];
#pragma unroll
        for (int o = 16; o > 0; o >>= 1) s += __shfl_xor_sync(0xffffffffu, s, o);
        if (lane == 0) g_proc[b * 256 + j] = 0.1f * (s + b2[j]);
    }
}

// ---------------- direct 3x3 conv, H=12 W=40 ----------------
// PAD: 0 = zero pad, 1 = reflect pad. ACT: 0 = relu, 1 = elu. ADDPROC: add 0.1*proc[b][ci] to input.
// grid (3 row-tiles, COUT/64, B), block 256.
template <int CIN, int COUT, int ACT, int PAD, bool ADDPROC>
__global__ void conv3_kernel(const float* __restrict__ in,
                             const float* __restrict__ w,
                             const float* __restrict__ bias,
                             float* __restrict__ out)
{
    const int b   = blockIdx.z;
    const int co0 = blockIdx.y * 64;
    const int r0  = blockIdx.x * 4;
    const int t   = threadIdx.x;
    const int ty  = t >> 4;        // co group: 4 co each
    const int px  = t & 15;
    const int pr  = px >> 2;       // row within tile (0..3)
    const int pc  = px & 3;        // col group: cols pc*10 .. pc*10+9
    const int row  = r0 + pr;
    const int col0 = pc * 10;

    __shared__ float s_in[8][6][44];   // [ci][row-1..row+4][col -1..40] at idx cc = gc+1
    __shared__ float s_w[64][73];      // [co][ci*9 + ky*3 + kx], pad 73 to avoid conflicts

    float acc[4][10];
#pragma unroll
    for (int i = 0; i < 4; i++)
#pragma unroll
        for (int j = 0; j < 10; j++) acc[i][j] = 0.f;

    const float* inB = in + (size_t)b * CIN * 480u;

    for (int ci0 = 0; ci0 < CIN; ci0 += 8) {
        __syncthreads();
        // weights: 64co x (8ci x 9) contiguous per co in global
        for (int idx = t; idx < 64 * 72; idx += 256) {
            int co = idx / 72;
            int r  = idx % 72;
            s_w[co][r] = w[((size_t)(co0 + co) * CIN + ci0) * 9u + r];
        }
        // input halo tile: 8ci x 6rows x 42cols
        for (int idx = t; idx < 8 * 6 * 42; idx += 256) {
            int ci = idx / (6 * 42);
            int rr = (idx / 42) % 6;
            int cc = idx % 42;
            int gr = r0 - 1 + rr;
            int gc = cc - 1;
            float v;
            if (PAD == 0) {
                if (gr < 0 || gr >= 12 || gc < 0 || gc >= 40) {
                    v = 0.f;
                } else {
                    v = inB[(size_t)(ci0 + ci) * 480u + gr * 40 + gc];
                    if (ADDPROC) v += g_proc[b * 256 + ci0 + ci];
                }
            } else {
                if (gr < 0) gr = -gr;
                if (gr >= 12) gr = 22 - gr;
                if (gc < 0) gc = -gc;
                if (gc >= 40) gc = 78 - gc;
                v = inB[(size_t)(ci0 + ci) * 480u + gr * 40 + gc];
                if (ADDPROC) v += g_proc[b * 256 + ci0 + ci];
            }
            s_in[ci][rr][cc] = v;
        }
        __syncthreads();

#pragma unroll
        for (int ci = 0; ci < 8; ci++) {
#pragma unroll
            for (int ky = 0; ky < 3; ky++) {
                float v[12];
#pragma unroll
                for (int jj = 0; jj < 12; jj++) v[jj] = s_in[ci][pr + ky][col0 + jj];
#pragma unroll
                for (int kx = 0; kx < 3; kx++) {
                    float wv[4];
#pragma unroll
                    for (int i = 0; i < 4; i++) wv[i] = s_w[ty * 4 + i][ci * 9 + ky * 3 + kx];
#pragma unroll
                    for (int i = 0; i < 4; i++)
#pragma unroll
                        for (int j = 0; j < 10; j++)
                            acc[i][j] = fmaf(wv[i], v[kx + j], acc[i][j]);
                }
            }
        }
    }

    float* outB = out + (size_t)b * COUT * 480u;
#pragma unroll
    for (int i = 0; i < 4; i++) {
        int co = co0 + ty * 4 + i;
        float bb = bias[co];
#pragma unroll
        for (int j = 0; j < 10; j++) {
            float x = acc[i][j] + bb;
            if (ACT == 0) x = fmaxf(x, 0.f);
            else          x = (x > 0.f) ? x : expm1f(x);
            outB[(size_t)co * 480u + row * 40 + col0 + j] = x;
        }
    }
}

// ---------------- pose2 (1x1 conv of pooled t1) ----------------
__global__ void pose2_kernel(const float* __restrict__ w, const float* __restrict__ bias)
{
    int b = blockIdx.x;
    int lane = threadIdx.x;   // block = 32
    const float* tp = g_t1pool + b * 256;
    for (int k = 0; k < 12; k++) {
        float s = 0.f;
        const float* wr = w + (size_t)k * 256u;
        for (int c = lane; c < 256; c += 32) s += tp[c] * wr[c];
#pragma unroll
        for (int o = 16; o > 0; o >>= 1) s += __shfl_xor_sync(0xffffffffu, s, o);
        if (lane == 0) g_out12[b * 12 + k] = s + bias[k];
    }
}

// ---------------- final: scale + pose outputs ----------------
__global__ void final_kernel(const float* __restrict__ lw, const float* __restrict__ lb,
                             float* __restrict__ outbuf)
{
    int b = threadIdx.x;   // 256 threads, 1 block
    float s = 0.f;
    const float* sf = g_sfeat + b * 64;
#pragma unroll
    for (int c = 0; c < 64; c++) s += sf[c] * lw[c];
    s += lb[0];
    float sig = 1.0f / (1.0f + expf(-s));
    float scale = expf(sig * (LOG_HI - LOG_LO) + LOG_LO);

    float* aa = outbuf;           // axisangle: (256,2,1,3)
    float* tr = outbuf + 1536;    // translation: (256,2,1,3)
#pragma unroll
    for (int u = 0; u < 2; u++) {
#pragma unroll
        for (int m = 0; m < 6; m++) {
            float v = 0.001f * g_out12[b * 12 + u * 6 + m] * scale;
            if (m < 3) aa[(b * 2 + u) * 3 + m]       = v;
            else       tr[(b * 2 + u) * 3 + (m - 3)] = v;
        }
    }
    outbuf[3072 + b] = scale;     // scale: (256,1)
}

// ---------------- launch ----------------
extern "C" void kernel_launch(void* const* d_in, const int* in_sizes, int n_in,
                              void* d_out, int out_size)
{
    (void)in_sizes; (void)n_in; (void)out_size;
    const float* f0         = (const float*)d_in[0];
    const float* squeeze_w  = (const float*)d_in[1];
    const float* squeeze_b  = (const float*)d_in[2];
    const float* pose0_w    = (const float*)d_in[3];
    const float* pose0_b    = (const float*)d_in[4];
    const float* pose1_w    = (const float*)d_in[5];
    const float* pose1_b    = (const float*)d_in[6];
    const float* pose2_w    = (const float*)d_in[7];
    const float* pose2_b    = (const float*)d_in[8];
    const float* fusion_w1  = (const float*)d_in[9];
    const float* fusion_b1  = (const float*)d_in[10];
    const float* fusion_w2  = (const float*)d_in[11];
    const float* fusion_b2  = (const float*)d_in[12];
    const float* bank       = (const float*)d_in[13];
    const float* scale_w1   = (const float*)d_in[14];
    const float* scale_b1   = (const float*)d_in[15];
    const float* scale_w2   = (const float*)d_in[16];
    const float* scale_b2   = (const float*)d_in[17];
    const float* scale_lw   = (const float*)d_in[18];
    const float* scale_lb   = (const float*)d_in[19];
    float* out = (float*)d_out;

    void *p_cat, *p_t0, *p_t1, *p_s1, *p_s2;
    cudaGetSymbolAddress(&p_cat, g_cat);
    cudaGetSymbolAddress(&p_t0,  g_t0);
    cudaGetSymbolAddress(&p_t1,  g_t1);
    cudaGetSymbolAddress(&p_s1,  g_s1);
    cudaGetSymbolAddress(&p_s2,  g_s2);
    void *p_pooled, *p_t1pool, *p_sfeat;
    cudaGetSymbolAddress(&p_pooled, g_pooled);
    cudaGetSymbolAddress(&p_t1pool, g_t1pool);
    cudaGetSymbolAddress(&p_sfeat,  g_sfeat);

    // squeeze + pooled
    squeeze_kernel<<<dim3(5, 4, 256), 256>>>(f0, squeeze_w, squeeze_b);
    pool_kernel<<<(65536 + 7) / 8, 256>>>((const float*)p_cat, (float*)p_pooled, 65536);

    // KNN + fusion MLP -> g_proc (= 0.1*proc)
    banknorm_kernel<<<125, 256>>>(bank);
    knn_fusion_kernel<<<256, 256>>>(bank, fusion_w1, fusion_b1, fusion_w2, fusion_b2);

    // pose branch
    conv3_kernel<256, 256, 0, 0, true ><<<dim3(3, 4, 256), 256>>>((const float*)p_cat, pose0_w, pose0_b, (float*)p_t0);
    conv3_kernel<256, 256, 0, 0, false><<<dim3(3, 4, 256), 256>>>((const float*)p_t0, pose1_w, pose1_b, (float*)p_t1);
    pool_kernel<<<(65536 + 7) / 8, 256>>>((const float*)p_t1, (float*)p_t1pool, 65536);
    pose2_kernel<<<256, 32>>>(pose2_w, pose2_b);

    // scale branch
    conv3_kernel<256, 128, 1, 1, true ><<<dim3(3, 2, 256), 256>>>((const float*)p_cat, scale_w1, scale_b1, (float*)p_s1);
    conv3_kernel<128, 64,  1, 1, false><<<dim3(3, 1, 256), 256>>>((const float*)p_s1, scale_w2, scale_b2, (float*)p_s2);
    pool_kernel<<<(16384 + 7) / 8, 256>>>((const float*)p_s2, (float*)p_sfeat, 16384);

    // final assembly
    final_kernel<<<1, 256>>>(scale_lw, scale_lb, out);
}